// round 4
// baseline (speedup 1.0000x reference)
#include <cuda_runtime.h>
#include <cstdint>

#define QN 16
#define QP 8            // query pairs
#define DD 384
#define NCOL 1000000
#define TN 2
#define TPB 256
#define PREF 8
#define COLS_PER_BLOCK (TPB * TN)   // 512
#define NBLK ((NCOL + COLS_PER_BLOCK - 1) / COLS_PER_BLOCK)  // 1954

__device__ __forceinline__ float neg_inf() { return __int_as_float(0xff800000); }

struct __align__(16) Top2 {
    float v1;
    float v2;
    int   i1;
    int   i2;
};

__device__ Top2 g_part[NBLK * QN];

__device__ __forceinline__ bool before(float va, int ia, float vb, int ib) {
    return (va > vb) || (va == vb && ia < ib);
}

__device__ __forceinline__ void merge_one(float& v1, int& i1, float& v2, int& i2,
                                          float s, int idx) {
    if (before(s, idx, v1, i1)) {
        v2 = v1; i2 = i1; v1 = s; i1 = idx;
    } else if (before(s, idx, v2, i2)) {
        v2 = s; i2 = idx;
    }
}

__device__ __forceinline__ void merge_pair(float& v1, int& i1, float& v2, int& i2,
                                           float w1, int j1, float w2, int j2) {
    merge_one(v1, i1, v2, i2, w1, j1);
    merge_one(v1, i1, v2, i2, w2, j2);
}

// ---------------------------------------------------------------------------
// Main kernel: per-block q-normalization preamble, then streaming similarity.
// TN=2 columns/thread, depth-8 LDG.64 prefetch ring, query-pair packed f32x2.
// ~80 regs -> 3 blocks/SM (24 warps) for latency hiding.
// ---------------------------------------------------------------------------
__global__ __launch_bounds__(TPB, 3) void sim_kernel(const float* __restrict__ q,
                                                     const float* __restrict__ bank,
                                                     const int* __restrict__ startp,
                                                     const int* __restrict__ endp) {
    // qs[d][p] = {qn[2p][d], qn[2p+1][d]}  (24 KB)
    __shared__ __align__(16) float2 qs[DD * QP];

    // --- preamble: L1-normalize queries (each warp owns query pair w) ---
    {
        const int w = threadIdx.x >> 5;    // 0..7 = pair index
        const int lane = threadIdx.x & 31;
        const float* q0 = q + (2 * w) * DD;
        const float* q1 = q + (2 * w + 1) * DD;
        float s0 = 0.f, s1 = 0.f;
        #pragma unroll
        for (int d = lane; d < DD; d += 32) {
            s0 += fabsf(q0[d]);
            s1 += fabsf(q1[d]);
        }
        #pragma unroll
        for (int o = 16; o; o >>= 1) {
            s0 += __shfl_xor_sync(0xffffffffu, s0, o);
            s1 += __shfl_xor_sync(0xffffffffu, s1, o);
        }
        const float inv0 = 1.0f / fmaxf(s0, 1e-12f);
        const float inv1 = 1.0f / fmaxf(s1, 1e-12f);
        #pragma unroll
        for (int d = lane; d < DD; d += 32)
            qs[d * QP + w] = make_float2(q0[d] * inv0, q1[d] * inv1);
    }
    __syncthreads();

    const int start = startp ? *startp : 400000;
    const int end   = endp   ? *endp   : 450000;

    const int n0 = blockIdx.x * COLS_PER_BLOCK + threadIdx.x * TN;

    // acc0[p] = {sim[2p][n0],   sim[2p+1][n0]}
    // acc1[p] = {sim[2p][n0+1], sim[2p+1][n0+1]}
    unsigned long long acc0[QP], acc1[QP];
    #pragma unroll
    for (int p = 0; p < QP; ++p) { acc0[p] = 0ull; acc1[p] = 0ull; }

    const bool active = (n0 < NCOL) && !(n0 >= start && n0 + TN <= end);
    if (active) {
        const float* p0 = bank + n0;
        float2 buf[PREF];
        #pragma unroll
        for (int p = 0; p < PREF; ++p)
            buf[p] = __ldcs(reinterpret_cast<const float2*>(p0 + (size_t)p * NCOL));
        const float* ppref = p0 + (size_t)PREF * NCOL;

        const ulonglong2* qsu = reinterpret_cast<const ulonglong2*>(qs);

        #pragma unroll 4
        for (int d = 0; d < DD - PREF; ++d) {
            float2 b = buf[d & (PREF - 1)];
            buf[d & (PREF - 1)] = __ldcs(reinterpret_cast<const float2*>(ppref));
            ppref += NCOL;

            unsigned long long bd0, bd1;
            asm("mov.b64 %0, {%1, %1};" : "=l"(bd0) : "f"(b.x));
            asm("mov.b64 %0, {%1, %1};" : "=l"(bd1) : "f"(b.y));

            const ulonglong2* qrow = qsu + d * (QP / 2);
            #pragma unroll
            for (int ph = 0; ph < QP / 2; ++ph) {
                ulonglong2 qq = qrow[ph];
                asm("fma.rn.f32x2 %0, %1, %2, %0;"
                    : "+l"(acc0[2 * ph]) : "l"(qq.x), "l"(bd0));
                asm("fma.rn.f32x2 %0, %1, %2, %0;"
                    : "+l"(acc1[2 * ph]) : "l"(qq.x), "l"(bd1));
                asm("fma.rn.f32x2 %0, %1, %2, %0;"
                    : "+l"(acc0[2 * ph + 1]) : "l"(qq.y), "l"(bd0));
                asm("fma.rn.f32x2 %0, %1, %2, %0;"
                    : "+l"(acc1[2 * ph + 1]) : "l"(qq.y), "l"(bd1));
            }
        }
        // drain ring
        #pragma unroll
        for (int d = DD - PREF; d < DD; ++d) {
            float2 b = buf[d & (PREF - 1)];
            unsigned long long bd0, bd1;
            asm("mov.b64 %0, {%1, %1};" : "=l"(bd0) : "f"(b.x));
            asm("mov.b64 %0, {%1, %1};" : "=l"(bd1) : "f"(b.y));
            const ulonglong2* qrow = qsu + d * (QP / 2);
            #pragma unroll
            for (int ph = 0; ph < QP / 2; ++ph) {
                ulonglong2 qq = qrow[ph];
                asm("fma.rn.f32x2 %0, %1, %2, %0;"
                    : "+l"(acc0[2 * ph]) : "l"(qq.x), "l"(bd0));
                asm("fma.rn.f32x2 %0, %1, %2, %0;"
                    : "+l"(acc1[2 * ph]) : "l"(qq.x), "l"(bd1));
                asm("fma.rn.f32x2 %0, %1, %2, %0;"
                    : "+l"(acc0[2 * ph + 1]) : "l"(qq.y), "l"(bd0));
                asm("fma.rn.f32x2 %0, %1, %2, %0;"
                    : "+l"(acc1[2 * ph + 1]) : "l"(qq.y), "l"(bd1));
            }
        }
    }

    bool ok[TN];
    #pragma unroll
    for (int c = 0; c < TN; ++c) {
        int col = n0 + c;
        ok[c] = active && (col < NCOL) && !(col >= start && col < end);
    }

    __syncthreads();  // done reading qs — reuse as reduction scratch
    Top2* sred = reinterpret_cast<Top2*>(qs);  // [8 warps][16 queries]
    const int warp = threadIdx.x >> 5;
    const int lane = threadIdx.x & 31;

    #pragma unroll
    for (int qi = 0; qi < QN; ++qi) {
        const int p = qi >> 1;
        const int h = qi & 1;
        float a0, a1;
        {
            float lo, hi;
            asm("mov.b64 {%0, %1}, %2;" : "=f"(lo), "=f"(hi) : "l"(acc0[p]));
            a0 = h ? hi : lo;
            asm("mov.b64 {%0, %1}, %2;" : "=f"(lo), "=f"(hi) : "l"(acc1[p]));
            a1 = h ? hi : lo;
        }
        float v1 = neg_inf(), v2 = neg_inf();
        int i1 = 0x7fffffff, i2 = 0x7fffffff;
        if (ok[0]) merge_one(v1, i1, v2, i2, a0, n0 + 0);
        if (ok[1]) merge_one(v1, i1, v2, i2, a1, n0 + 1);
        #pragma unroll
        for (int off = 16; off; off >>= 1) {
            float w1 = __shfl_down_sync(0xffffffffu, v1, off);
            int   j1 = __shfl_down_sync(0xffffffffu, i1, off);
            float w2 = __shfl_down_sync(0xffffffffu, v2, off);
            int   j2 = __shfl_down_sync(0xffffffffu, i2, off);
            merge_pair(v1, i1, v2, i2, w1, j1, w2, j2);
        }
        if (lane == 0) {
            Top2 t; t.v1 = v1; t.v2 = v2; t.i1 = i1; t.i2 = i2;
            sred[warp * QN + qi] = t;
        }
    }
    __syncthreads();

    if (threadIdx.x < QN) {
        const int qi = threadIdx.x;
        float v1 = neg_inf(), v2 = neg_inf();
        int i1 = 0x7fffffff, i2 = 0x7fffffff;
        #pragma unroll
        for (int w = 0; w < TPB / 32; ++w) {
            Top2 t = sred[w * QN + qi];
            merge_pair(v1, i1, v2, i2, t.v1, t.i1, t.v2, t.i2);
        }
        Top2 r; r.v1 = v1; r.v2 = v2; r.i1 = i1; r.i2 = i2;
        g_part[blockIdx.x * QN + qi] = r;
    }
}

// ---------------------------------------------------------------------------
// Final merge: one block per query, 256 threads strided over NBLK partials.
// ---------------------------------------------------------------------------
__global__ void final_kernel(float* __restrict__ out, int nblocks) {
    const int qi = blockIdx.x;          // 0..15
    const int tid = threadIdx.x;        // 256
    const int warp = tid >> 5;
    const int lane = tid & 31;

    float v1 = neg_inf(), v2 = neg_inf();
    int i1 = 0x7fffffff, i2 = 0x7fffffff;
    for (int b = tid; b < nblocks; b += 256) {
        Top2 t = g_part[b * QN + qi];
        merge_pair(v1, i1, v2, i2, t.v1, t.i1, t.v2, t.i2);
    }
    #pragma unroll
    for (int off = 16; off; off >>= 1) {
        float w1 = __shfl_down_sync(0xffffffffu, v1, off);
        int   j1 = __shfl_down_sync(0xffffffffu, i1, off);
        float w2 = __shfl_down_sync(0xffffffffu, v2, off);
        int   j2 = __shfl_down_sync(0xffffffffu, i2, off);
        merge_pair(v1, i1, v2, i2, w1, j1, w2, j2);
    }
    __shared__ Top2 s[8];
    if (lane == 0) {
        Top2 t; t.v1 = v1; t.v2 = v2; t.i1 = i1; t.i2 = i2;
        s[warp] = t;
    }
    __syncthreads();
    if (tid == 0) {
        Top2 r = s[0];
        #pragma unroll
        for (int w = 1; w < 8; ++w)
            merge_pair(r.v1, r.i1, r.v2, r.i2, s[w].v1, s[w].i1, s[w].v2, s[w].i2);
        out[qi * 2 + 0] = r.v1;
        out[qi * 2 + 1] = r.v2;
        out[QN * 2 + qi * 2 + 0] = (float)r.i1;
        out[QN * 2 + qi * 2 + 1] = (float)r.i2;
    }
}

extern "C" void kernel_launch(void* const* d_in, const int* in_sizes, int n_in,
                              void* d_out, int out_size) {
    const float* q    = (const float*)d_in[0];
    const float* bank = (const float*)d_in[1];
    const int* startp = (n_in > 2) ? (const int*)d_in[2] : nullptr;
    const int* endp   = (n_in > 3) ? (const int*)d_in[3] : nullptr;
    float* out = (float*)d_out;

    sim_kernel<<<NBLK, TPB>>>(q, bank, startp, endp);
    final_kernel<<<QN, 256>>>(out, NBLK);
}

// round 5
// speedup vs baseline: 3.6365x; 3.6365x over previous
#include <cuda_runtime.h>
#include <cstdint>

#define QN 16
#define DD 384
#define NCOL 1000000
#define TPB 256
#define NWARP 8
#define CPB 256                                   // cols per block
#define NBLK ((NCOL + CPB - 1) / CPB)             // 3907
#define NK (DD / 8)                               // 48 k-groups
#define NSTAGE 4
#define SB_STRIDE 264                             // 256 + 8 pad (conflict-free)
#define SB_TILE (8 * SB_STRIDE)
#define QS_STRIDE 17

#define QS_FLOATS (DD * QS_STRIDE)                // 6528
#define SB_FLOATS (NSTAGE * SB_TILE)              // 8448
#define SMEM_BYTES (QS_FLOATS * 4 + SB_FLOATS * 4 + NWARP * 16 * 16)

__device__ __forceinline__ float neg_inf() { return __int_as_float(0xff800000); }

struct __align__(16) Top2 {
    float v1;
    float v2;
    int   i1;
    int   i2;
};

__device__ Top2 g_part[NBLK * QN];

__device__ __forceinline__ bool before(float va, int ia, float vb, int ib) {
    return (va > vb) || (va == vb && ia < ib);
}

__device__ __forceinline__ void merge_one(float& v1, int& i1, float& v2, int& i2,
                                          float s, int idx) {
    if (before(s, idx, v1, i1)) {
        v2 = v1; i2 = i1; v1 = s; i1 = idx;
    } else if (before(s, idx, v2, i2)) {
        v2 = s; i2 = idx;
    }
}

__device__ __forceinline__ void merge_pair(float& v1, int& i1, float& v2, int& i2,
                                           float w1, int j1, float w2, int j2) {
    merge_one(v1, i1, v2, i2, w1, j1);
    merge_one(v1, i1, v2, i2, w2, j2);
}

__device__ __forceinline__ float tf32_trunc(float x) {
    return __uint_as_float(__float_as_uint(x) & 0xffffe000u);
}

__device__ __forceinline__ void mma_tf32(float* c, const uint32_t* a,
                                         uint32_t b0, uint32_t b1) {
    asm volatile(
        "mma.sync.aligned.m16n8k8.row.col.f32.tf32.tf32.f32 "
        "{%0,%1,%2,%3}, {%4,%5,%6,%7}, {%8,%9}, {%0,%1,%2,%3};"
        : "+f"(c[0]), "+f"(c[1]), "+f"(c[2]), "+f"(c[3])
        : "r"(a[0]), "r"(a[1]), "r"(a[2]), "r"(a[3]), "r"(b0), "r"(b1));
}

__device__ __forceinline__ void cp16(uint32_t dst, const float* src) {
    asm volatile("cp.async.cg.shared.global [%0], [%1], 16;" :: "r"(dst), "l"(src));
}

// ---------------------------------------------------------------------------
// Main kernel: 3xTF32 split GEMM. Per block: 256 cols x D=384, 8 warps of 32
// cols each. Bank streamed via 4-stage cp.async pipeline (8 rows x 256 cols).
// ---------------------------------------------------------------------------
__global__ __launch_bounds__(TPB, 2) void sim_kernel(const float* __restrict__ q,
                                                     const float* __restrict__ bank,
                                                     const int* __restrict__ startp,
                                                     const int* __restrict__ endp) {
    extern __shared__ __align__(16) float smem[];
    float* qs = smem;                          // [DD][QS_STRIDE]
    float* sB = smem + QS_FLOATS;              // [NSTAGE][8][SB_STRIDE]
    Top2* sred = reinterpret_cast<Top2*>(smem + QS_FLOATS + SB_FLOATS);  // [8][16]

    const int start = startp ? *startp : 400000;
    const int end   = endp   ? *endp   : 450000;
    const int cb = blockIdx.x * CPB;
    const int tid = threadIdx.x;

    // Whole block inside exclusion window -> emit sentinels and exit.
    if (cb >= start && cb + CPB <= end) {
        if (tid < QN) {
            Top2 t;
            t.v1 = neg_inf(); t.v2 = neg_inf();
            t.i1 = 0x7fffffff; t.i2 = 0x7fffffff;
            g_part[blockIdx.x * QN + tid] = t;
        }
        return;
    }

    // --- normalize queries into qs[d][qrow] ---
    {
        const int w = tid >> 5;      // warp handles queries 2w, 2w+1
        const int lane = tid & 31;
        const float* q0 = q + (2 * w) * DD;
        const float* q1 = q + (2 * w + 1) * DD;
        float s0 = 0.f, s1 = 0.f;
        #pragma unroll
        for (int d = lane; d < DD; d += 32) {
            s0 += fabsf(q0[d]);
            s1 += fabsf(q1[d]);
        }
        #pragma unroll
        for (int o = 16; o; o >>= 1) {
            s0 += __shfl_xor_sync(0xffffffffu, s0, o);
            s1 += __shfl_xor_sync(0xffffffffu, s1, o);
        }
        const float inv0 = 1.0f / fmaxf(s0, 1e-12f);
        const float inv1 = 1.0f / fmaxf(s1, 1e-12f);
        #pragma unroll
        for (int d = lane; d < DD; d += 32) {
            qs[d * QS_STRIDE + 2 * w]     = q0[d] * inv0;
            qs[d * QS_STRIDE + 2 * w + 1] = q1[d] * inv1;
        }
    }

    // staging coordinates for this thread (2 x 16B per stage)
    const int srow = tid >> 5;                 // 0..7
    const int scol = (tid & 31) * 8;           // 0..248
    int gc = cb + scol;
    if (gc > NCOL - 8) gc = NCOL - 8;          // clamp (garbage masked later)
    const float* gsrc = bank + (size_t)srow * NCOL + gc;
    uint32_t sbase = (uint32_t)__cvta_generic_to_shared(sB) +
                     (srow * SB_STRIDE + scol) * 4;

    // prologue: stages 0..2
    #pragma unroll
    for (int s = 0; s < NSTAGE - 1; ++s) {
        const float* src = gsrc + (size_t)(s * 8) * NCOL;
        uint32_t dst = sbase + s * (SB_TILE * 4);
        cp16(dst, src);
        cp16(dst + 16, src + 4);
        asm volatile("cp.async.commit_group;" ::: "memory");
    }

    const int lane = tid & 31;
    const int wid = tid >> 5;
    const int tk = lane & 3;                   // thread-in-group (k index)
    const int g  = lane >> 2;                  // group id (row / n index)

    float c[4][4];
    #pragma unroll
    for (int nt = 0; nt < 4; ++nt)
        #pragma unroll
        for (int i = 0; i < 4; ++i) c[nt][i] = 0.f;

    for (int kg = 0; kg < NK; ++kg) {
        asm volatile("cp.async.wait_group 2;" ::: "memory");
        __syncthreads();

        // issue stage kg+3 (overwrites buffer used by compute kg-1; safe after sync)
        if (kg + NSTAGE - 1 < NK) {
            const float* src = gsrc + (size_t)((kg + NSTAGE - 1) * 8) * NCOL;
            uint32_t dst = sbase + ((kg + NSTAGE - 1) & (NSTAGE - 1)) * (SB_TILE * 4);
            cp16(dst, src);
            cp16(dst + 16, src + 4);
        }
        asm volatile("cp.async.commit_group;" ::: "memory");

        // --- A fragments (queries), hi = raw (HW truncates), lo = residual ---
        const float* qb = qs + (kg * 8) * QS_STRIDE;
        float q00 = qb[tk * QS_STRIDE + g];              // a0: (row g,   k tk)
        float q10 = qb[tk * QS_STRIDE + g + 8];          // a1: (row g+8, k tk)
        float q01 = qb[(tk + 4) * QS_STRIDE + g];        // a2: (row g,   k tk+4)
        float q11 = qb[(tk + 4) * QS_STRIDE + g + 8];    // a3: (row g+8, k tk+4)
        uint32_t ah[4] = {__float_as_uint(q00), __float_as_uint(q10),
                          __float_as_uint(q01), __float_as_uint(q11)};
        uint32_t al[4] = {__float_as_uint(q00 - tf32_trunc(q00)),
                          __float_as_uint(q10 - tf32_trunc(q10)),
                          __float_as_uint(q01 - tf32_trunc(q01)),
                          __float_as_uint(q11 - tf32_trunc(q11))};

        const float* sb = sB + (kg & (NSTAGE - 1)) * SB_TILE;
        #pragma unroll
        for (int nt = 0; nt < 4; ++nt) {
            const int cB = wid * 32 + nt * 8 + g;
            float b0 = sb[tk * SB_STRIDE + cB];
            float b1 = sb[(tk + 4) * SB_STRIDE + cB];
            uint32_t b0b = __float_as_uint(b0);
            uint32_t b1b = __float_as_uint(b1);
            uint32_t bl0 = __float_as_uint(b0 - tf32_trunc(b0));
            uint32_t bl1 = __float_as_uint(b1 - tf32_trunc(b1));
            mma_tf32(c[nt], ah, b0b, b1b);   // hi*hi
            mma_tf32(c[nt], ah, bl0, bl1);   // hi*lo
            mma_tf32(c[nt], al, b0b, b1b);   // lo*hi
        }
    }

    // --- epilogue: per-thread top2 for rows g and g+8, quad reduce ---
    float v1l = neg_inf(), v2l = neg_inf();
    int i1l = 0x7fffffff, i2l = 0x7fffffff;
    float v1h = neg_inf(), v2h = neg_inf();
    int i1h = 0x7fffffff, i2h = 0x7fffffff;

    #pragma unroll
    for (int nt = 0; nt < 4; ++nt) {
        const int col0 = cb + wid * 32 + nt * 8 + 2 * tk;
        const int col1 = col0 + 1;
        const bool ok0 = (col0 < NCOL) && !(col0 >= start && col0 < end);
        const bool ok1 = (col1 < NCOL) && !(col1 >= start && col1 < end);
        if (ok0) {
            merge_one(v1l, i1l, v2l, i2l, c[nt][0], col0);
            merge_one(v1h, i1h, v2h, i2h, c[nt][2], col0);
        }
        if (ok1) {
            merge_one(v1l, i1l, v2l, i2l, c[nt][1], col1);
            merge_one(v1h, i1h, v2h, i2h, c[nt][3], col1);
        }
    }
    #pragma unroll
    for (int off = 1; off <= 2; off <<= 1) {
        float w1, w2; int j1, j2;
        w1 = __shfl_xor_sync(0xffffffffu, v1l, off);
        j1 = __shfl_xor_sync(0xffffffffu, i1l, off);
        w2 = __shfl_xor_sync(0xffffffffu, v2l, off);
        j2 = __shfl_xor_sync(0xffffffffu, i2l, off);
        merge_pair(v1l, i1l, v2l, i2l, w1, j1, w2, j2);
        w1 = __shfl_xor_sync(0xffffffffu, v1h, off);
        j1 = __shfl_xor_sync(0xffffffffu, i1h, off);
        w2 = __shfl_xor_sync(0xffffffffu, v2h, off);
        j2 = __shfl_xor_sync(0xffffffffu, i2h, off);
        merge_pair(v1h, i1h, v2h, i2h, w1, j1, w2, j2);
    }
    __syncthreads();   // all compute done before reusing smem region
    if (tk == 0) {
        Top2 tl; tl.v1 = v1l; tl.v2 = v2l; tl.i1 = i1l; tl.i2 = i2l;
        sred[wid * 16 + g] = tl;
        Top2 th; th.v1 = v1h; th.v2 = v2h; th.i1 = i1h; th.i2 = i2h;
        sred[wid * 16 + 8 + g] = th;
    }
    __syncthreads();

    if (tid < QN) {
        float v1 = neg_inf(), v2 = neg_inf();
        int i1 = 0x7fffffff, i2 = 0x7fffffff;
        #pragma unroll
        for (int w = 0; w < NWARP; ++w) {
            Top2 t = sred[w * 16 + tid];
            merge_pair(v1, i1, v2, i2, t.v1, t.i1, t.v2, t.i2);
        }
        Top2 r; r.v1 = v1; r.v2 = v2; r.i1 = i1; r.i2 = i2;
        g_part[blockIdx.x * QN + tid] = r;
    }
}

// ---------------------------------------------------------------------------
// Final merge: one block per query, 256 threads strided over NBLK partials.
// ---------------------------------------------------------------------------
__global__ void final_kernel(float* __restrict__ out, int nblocks) {
    const int qi = blockIdx.x;
    const int tid = threadIdx.x;
    const int warp = tid >> 5;
    const int lane = tid & 31;

    float v1 = neg_inf(), v2 = neg_inf();
    int i1 = 0x7fffffff, i2 = 0x7fffffff;
    for (int b = tid; b < nblocks; b += 256) {
        Top2 t = g_part[b * QN + qi];
        merge_pair(v1, i1, v2, i2, t.v1, t.i1, t.v2, t.i2);
    }
    #pragma unroll
    for (int off = 16; off; off >>= 1) {
        float w1 = __shfl_down_sync(0xffffffffu, v1, off);
        int   j1 = __shfl_down_sync(0xffffffffu, i1, off);
        float w2 = __shfl_down_sync(0xffffffffu, v2, off);
        int   j2 = __shfl_down_sync(0xffffffffu, i2, off);
        merge_pair(v1, i1, v2, i2, w1, j1, w2, j2);
    }
    __shared__ Top2 s[8];
    if (lane == 0) {
        Top2 t; t.v1 = v1; t.v2 = v2; t.i1 = i1; t.i2 = i2;
        s[warp] = t;
    }
    __syncthreads();
    if (tid == 0) {
        Top2 r = s[0];
        #pragma unroll
        for (int w = 1; w < 8; ++w)
            merge_pair(r.v1, r.i1, r.v2, r.i2, s[w].v1, s[w].i1, s[w].v2, s[w].i2);
        out[qi * 2 + 0] = r.v1;
        out[qi * 2 + 1] = r.v2;
        out[QN * 2 + qi * 2 + 0] = (float)r.i1;
        out[QN * 2 + qi * 2 + 1] = (float)r.i2;
    }
}

extern "C" void kernel_launch(void* const* d_in, const int* in_sizes, int n_in,
                              void* d_out, int out_size) {
    const float* q    = (const float*)d_in[0];
    const float* bank = (const float*)d_in[1];
    const int* startp = (n_in > 2) ? (const int*)d_in[2] : nullptr;
    const int* endp   = (n_in > 3) ? (const int*)d_in[3] : nullptr;
    float* out = (float*)d_out;

    static int smem_set = 0;
    if (!smem_set) {
        cudaFuncSetAttribute(sim_kernel,
                             cudaFuncAttributeMaxDynamicSharedMemorySize,
                             SMEM_BYTES);
        smem_set = 1;
    }

    sim_kernel<<<NBLK, TPB, SMEM_BYTES>>>(q, bank, startp, endp);
    final_kernel<<<QN, 256>>>(out, NBLK);
}